// round 1
// baseline (speedup 1.0000x reference)
#include <cuda_runtime.h>
#include <cuda_bf16.h>
#include <math.h>

#define N_NODES_MAX 100000
#define N_EDGES_MAX 1600000
#define IN_FEATS 128
#define HD 128           // NUM_HEADS * OUT_FEATS
#define NEG_SLOPE 0.2f

// ---------------- scratch (device globals: alloc-free) ----------------
__device__ float g_ft[N_NODES_MAX * HD];     // projected features [N,128]
__device__ float g_el[N_NODES_MAX * 4];      // [N,H]
__device__ float g_er[N_NODES_MAX * 4];      // [N,H]
__device__ int   g_offs[N_NODES_MAX + 1];    // CSR offsets from sorted dst

// ---------------- 1) SGEMM: g_ft = feat @ W  (MxK @ KxN, K=N=128) ----------------
__global__ __launch_bounds__(256) void gemm_kernel(const float* __restrict__ A,
                                                   const float* __restrict__ B,
                                                   int M) {
    __shared__ float As[8][128];  // [k][m]
    __shared__ float Bs[8][128];  // [k][n]
    const int tid = threadIdx.x;
    const int bm  = blockIdx.x * 128;

    const int arow  = tid >> 1;          // 0..127
    const int acol4 = (tid & 1) * 4;     // 0 or 4
    const int brow  = tid >> 5;          // 0..7
    const int bcol4 = (tid & 31) * 4;    // 0..124
    const int ty = tid >> 4;             // 0..15
    const int tx = tid & 15;             // 0..15

    float acc[8][8];
#pragma unroll
    for (int i = 0; i < 8; i++)
#pragma unroll
        for (int j = 0; j < 8; j++) acc[i][j] = 0.f;

    for (int k0 = 0; k0 < 128; k0 += 8) {
        float4 av = make_float4(0.f, 0.f, 0.f, 0.f);
        int gr = bm + arow;
        if (gr < M) av = *(const float4*)(A + (size_t)gr * 128 + k0 + acol4);
        As[acol4 + 0][arow] = av.x;
        As[acol4 + 1][arow] = av.y;
        As[acol4 + 2][arow] = av.z;
        As[acol4 + 3][arow] = av.w;
        float4 bv = *(const float4*)(B + (size_t)(k0 + brow) * 128 + bcol4);
        *(float4*)(&Bs[brow][bcol4]) = bv;
        __syncthreads();

#pragma unroll
        for (int kk = 0; kk < 8; kk++) {
            float a[8], b[8];
            *(float4*)(a)     = *(const float4*)(&As[kk][ty * 8]);
            *(float4*)(a + 4) = *(const float4*)(&As[kk][ty * 8 + 4]);
            *(float4*)(b)     = *(const float4*)(&Bs[kk][tx * 8]);
            *(float4*)(b + 4) = *(const float4*)(&Bs[kk][tx * 8 + 4]);
#pragma unroll
            for (int i = 0; i < 8; i++)
#pragma unroll
                for (int j = 0; j < 8; j++) acc[i][j] = fmaf(a[i], b[j], acc[i][j]);
        }
        __syncthreads();
    }

#pragma unroll
    for (int i = 0; i < 8; i++) {
        int row = bm + ty * 8 + i;
        if (row < M) {
            float* dst = g_ft + (size_t)row * 128 + tx * 8;
            *(float4*)(dst)     = *(float4*)(&acc[i][0]);
            *(float4*)(dst + 4) = *(float4*)(&acc[i][4]);
        }
    }
}

// ---------------- 2) el/er: per (node, head) dot with attn vectors ----------------
__global__ void elr_kernel(const float* __restrict__ attn_l,
                           const float* __restrict__ attn_r, int N) {
    int t = blockIdx.x * blockDim.x + threadIdx.x;
    if (t >= N * 4) return;
    int n = t >> 2, h = t & 3;
    const float4* f  = (const float4*)(g_ft + (size_t)n * 128 + h * 32);
    const float4* al = (const float4*)(attn_l + h * 32);
    const float4* ar = (const float4*)(attn_r + h * 32);
    float sl = 0.f, sr = 0.f;
#pragma unroll
    for (int i = 0; i < 8; i++) {
        float4 fv = f[i];
        float4 lv = __ldg(al + i);
        float4 rv = __ldg(ar + i);
        sl += fv.x * lv.x + fv.y * lv.y + fv.z * lv.z + fv.w * lv.w;
        sr += fv.x * rv.x + fv.y * rv.y + fv.z * rv.z + fv.w * rv.w;
    }
    g_el[t] = sl;
    g_er[t] = sr;
}

// ---------------- 3) CSR offsets from sorted dst (binary search) ----------------
__global__ void offs_kernel(const int* __restrict__ dst, int N, int E) {
    int n = blockIdx.x * blockDim.x + threadIdx.x;
    if (n > N) return;
    int lo = 0, hi = E;
    while (lo < hi) {
        int mid = (lo + hi) >> 1;
        if (__ldg(dst + mid) < n) lo = mid + 1; else hi = mid;
    }
    g_offs[n] = lo;
}

// ---------------- 4) per-dst-node online-softmax aggregation (1 warp / node) ----
__global__ __launch_bounds__(256) void agg_kernel(const int* __restrict__ src,
                                                  float* __restrict__ out, int N) {
    int gid  = blockIdx.x * blockDim.x + threadIdx.x;
    int node = gid >> 5;
    int lane = gid & 31;
    if (node >= N) return;

    int h = lane >> 3;  // 8 lanes per head
    int s = g_offs[node];
    int e = g_offs[node + 1];

    float er_h = g_er[node * 4 + h];
    float m = -1e30f, ssum = 0.f;
    float4 acc = make_float4(0.f, 0.f, 0.f, 0.f);

    for (int i = s; i < e; i++) {
        int sn = __ldg(src + i);
        float sc = g_el[sn * 4 + h] + er_h;
        sc = sc > 0.f ? sc : NEG_SLOPE * sc;
        float m_new = fmaxf(m, sc);
        float corr  = __expf(m - m_new);     // 0 on first iter (m = -1e30)
        float p     = __expf(sc - m_new);
        ssum = ssum * corr + p;
        float4 f = *(const float4*)(g_ft + (size_t)sn * 128 + lane * 4);
        acc.x = acc.x * corr + p * f.x;
        acc.y = acc.y * corr + p * f.y;
        acc.z = acc.z * corr + p * f.z;
        acc.w = acc.w * corr + p * f.w;
        m = m_new;
    }

    float inv = (ssum > 0.f) ? (1.f / ssum) : 0.f;
    float4 o = make_float4(acc.x * inv, acc.y * inv, acc.z * inv, acc.w * inv);
    *(float4*)(out + (size_t)node * 128 + lane * 4) = o;
}

// ---------------- launch ----------------
extern "C" void kernel_launch(void* const* d_in, const int* in_sizes, int n_in,
                              void* d_out, int out_size) {
    const float* feat   = (const float*)d_in[0];
    const int*   src    = (const int*)d_in[1];
    const int*   dst    = (const int*)d_in[2];
    const float* W      = (const float*)d_in[3];
    const float* attn_l = (const float*)d_in[4];
    const float* attn_r = (const float*)d_in[5];
    float* out = (float*)d_out;

    int M = in_sizes[0] / IN_FEATS;   // nodes
    int E = in_sizes[1];              // edges

    gemm_kernel<<<(M + 127) / 128, 256>>>(feat, W, M);
    elr_kernel<<<(M * 4 + 255) / 256, 256>>>(attn_l, attn_r, M);
    offs_kernel<<<(M + 1 + 255) / 256, 256>>>(dst, M, E);
    agg_kernel<<<((M * 32) + 255) / 256, 256>>>(src, out, M);
}